// round 6
// baseline (speedup 1.0000x reference)
#include <cuda_runtime.h>
#include <math.h>
#include <cstdint>

#define Ndim 32
#define Cdim 512
#define Tdim 1024
#define NT   32768
#define NB   2048
#define CT   (Cdim*Tdim)
#define XSZ  (Ndim*Cdim*Tdim)

#define OFF_XD   0
#define OFF_LOSS 16777216
#define OFF_PERP 16777217
#define OFF_CB   16777218
#define OFF_CSE  (OFF_CB + NB*Cdim)
#define OFF_CNT  (OFF_CSE + NB*Cdim)

// Scratch (device globals: the sanctioned no-cudaMalloc path)
__device__ __align__(16) float g_cc[NB];
__device__ __align__(16) int   g_idx[NT];
__device__ __align__(16) float g_nsum[NB*Cdim];
__device__ __align__(16) float g_ncnt[NB];
__device__ float g_loss;
__device__ __align__(16) float g_xT[(size_t)NT * Cdim];   // 64 MB x transposed [row][c]

// ---------------------------------------------------------------- helpers
__device__ __forceinline__ void cp_async16(uint32_t saddr, const void* g) {
    asm volatile("cp.async.ca.shared.global [%0], [%1], 16;" :: "r"(saddr), "l"(g));
}
__device__ __forceinline__ void cp_commit() {
    asm volatile("cp.async.commit_group;" ::: "memory");
}
__device__ __forceinline__ void mma_tf32(float* d, const uint32_t* a, const uint32_t* b) {
    asm volatile(
        "mma.sync.aligned.m16n8k8.row.col.f32.tf32.tf32.f32 "
        "{%0,%1,%2,%3}, {%4,%5,%6,%7}, {%8,%9}, {%0,%1,%2,%3};"
        : "+f"(d[0]), "+f"(d[1]), "+f"(d[2]), "+f"(d[3])
        : "r"(a[0]), "r"(a[1]), "r"(a[2]), "r"(a[3]), "r"(b[0]), "r"(b[1]));
}
// monotonic float<->uint key (ascending)
__device__ __forceinline__ uint32_t ordkey(float f) {
    uint32_t u = __float_as_uint(f);
    return (u >> 31) ? ~u : (u | 0x80000000u);
}
__device__ __forceinline__ float orddec(uint32_t k) {
    uint32_t u = (k & 0x80000000u) ? (k & 0x7fffffffu) : ~k;
    return __uint_as_float(u);
}

// ---------------- 0: zero scratch ----------------
__global__ void zero_kernel() {
    int i = blockIdx.x * 256 + threadIdx.x;
    if (i < NB * Cdim) g_nsum[i] = 0.0f;
    if (i < NB)        g_ncnt[i] = 0.0f;
    if (i == 0)        g_loss = 0.0f;
}

// ---------------- 1: codebook squared norms ----------------
__global__ void norms_kernel(const float* __restrict__ cb) {
    int warp = threadIdx.x >> 5, lane = threadIdx.x & 31;
    int code = blockIdx.x * 8 + warp;
    const float* row = cb + (size_t)code * Cdim;
    float s = 0.0f;
    for (int j = lane; j < Cdim; j += 32) { float v = row[j]; s += v * v; }
    #pragma unroll
    for (int o = 16; o > 0; o >>= 1) s += __shfl_xor_sync(0xffffffffu, s, o);
    if (lane == 0) g_cc[code] = s;
}

// ---------------- 2: transpose x -> xT[row][c] ----------------
__global__ void transpose_kernel(const float* __restrict__ x) {
    __shared__ float s[32][33];
    int b = blockIdx.x;
    int ct = b & 15;
    int tt = (b >> 4) & 31;
    int n  = b >> 9;
    int tid = threadIdx.x;
    int l5 = tid & 31, h3 = tid >> 5;
    #pragma unroll
    for (int q = 0; q < 4; q++) {
        int c_l = h3 + q * 8;
        s[c_l][l5] = x[(size_t)n * CT + (size_t)(ct * 32 + c_l) * Tdim + tt * 32 + l5];
    }
    __syncthreads();
    #pragma unroll
    for (int q = 0; q < 4; q++) {
        int t_l = h3 + q * 8;
        g_xT[(size_t)(n * 1024 + tt * 32 + t_l) * Cdim + ct * 32 + l5] = s[l5][t_l];
    }
}

// ---------------- 3: fused TF32 screen GEMM + candidate argmin + exact rescue ----------------
// BM=128 rows x all 2048 codes (16 n-tiles), BK=32, 3-stage cp.async, 1 sync/iter.
// Screen d_hat never leaves the CTA: running-min + margin-8 candidate lists in smem,
// exact fp32 rescue at kernel end writes g_idx.
#define BM 128
#define BK 32
#define AS_STRIDE 136
#define BS_STRIDE 36
#define AS_FLOATS (BK * AS_STRIDE)                 // 4352
#define BS_FLOATS (128 * BS_STRIDE)                // 4608
#define STAGE_FLOATS (AS_FLOATS + BS_FLOATS)       // 8960
#define SMEM_BYTES (3 * STAGE_FLOATS * 4)          // 107520
#define CAP 16
#define MARGIN 8.0f

__global__ __launch_bounds__(256, 2) void gemm_argmin(const float* __restrict__ x,
                                                      const float* __restrict__ cb) {
    extern __shared__ float sm[];
    __shared__ uint32_t s_min[128];
    __shared__ int      s_cnt[128];
    __shared__ uint16_t s_cols[128][CAP];

    uint32_t smbase = (uint32_t)__cvta_generic_to_shared(sm);

    int tid = threadIdx.x, lane = tid & 31, wid = tid >> 5;
    int wm = wid >> 2, wn = wid & 3;
    int lq = lane & 3, lr = lane >> 2;
    int r0 = blockIdx.x * BM;
    const float* xb = x + (size_t)(r0 >> 10) * CT + (r0 & 1023);

    int a_p  = (tid & 31) << 2;
    int a_kb = tid >> 5;
    int b_kp = (tid & 7) << 2;
    int b_cb = tid >> 3;

    if (tid < 128) { s_min[tid] = 0xFFFFFFFFu; s_cnt[tid] = 0; }

    float acc[4][4][4];
    #pragma unroll
    for (int mi = 0; mi < 4; mi++)
        #pragma unroll
        for (int ni = 0; ni < 4; ni++)
            #pragma unroll
            for (int v = 0; v < 4; v++) acc[mi][ni][v] = 0.0f;

    auto load_tiles = [&](int buf, int idx) {
        int nt = (idx >> 4) * 128, kc = (idx & 15) * 32;
        uint32_t sA = smbase + (uint32_t)(buf * STAGE_FLOATS) * 4u;
        uint32_t sB = sA + (uint32_t)AS_FLOATS * 4u;
        #pragma unroll
        for (int it = 0; it < 4; it++) {
            int k = a_kb + it * 8;
            cp_async16(sA + (uint32_t)(k * AS_STRIDE + a_p) * 4u,
                       xb + (size_t)(kc + k) * Tdim + a_p);
        }
        #pragma unroll
        for (int it = 0; it < 4; it++) {
            int code = b_cb + it * 32;
            cp_async16(sB + (uint32_t)(code * BS_STRIDE + b_kp) * 4u,
                       cb + (size_t)(nt + code) * Cdim + kc + b_kp);
        }
    };

    load_tiles(0, 0); cp_commit();
    load_tiles(1, 1); cp_commit();

    for (int i = 0; i < 256; i++) {
        __syncthreads();                       // all warps done with stage (i-1)%3
        if (i + 2 < 256) load_tiles((i + 2) % 3, i + 2);
        cp_commit();                           // one group per iter (possibly empty)
        asm volatile("cp.async.wait_group 2;" ::: "memory");  // tile i resident

        const float* A = sm + (i % 3) * STAGE_FLOATS;
        const float* B = A + AS_FLOATS;
        #pragma unroll
        for (int kk = 0; kk < 4; kk++) {
            uint32_t a[4][4], b[4][2];
            #pragma unroll
            for (int mi = 0; mi < 4; mi++) {
                const float* ap = A + (kk * 8 + lq) * AS_STRIDE + wm * 64 + mi * 16 + lr;
                a[mi][0] = __float_as_uint(ap[0]);
                a[mi][1] = __float_as_uint(ap[8]);
                a[mi][2] = __float_as_uint(ap[4 * AS_STRIDE]);
                a[mi][3] = __float_as_uint(ap[4 * AS_STRIDE + 8]);
            }
            #pragma unroll
            for (int ni = 0; ni < 4; ni++) {
                const float* bp = B + (wn * 32 + ni * 8 + lr) * BS_STRIDE + kk * 8 + lq;
                b[ni][0] = __float_as_uint(bp[0]);
                b[ni][1] = __float_as_uint(bp[4]);
            }
            #pragma unroll
            for (int mi = 0; mi < 4; mi++)
                #pragma unroll
                for (int ni = 0; ni < 4; ni++)
                    mma_tf32(acc[mi][ni], a[mi], b[ni]);
        }

        if ((i & 15) == 15) {                  // end of K: screen this n-tile
            int nt = (i >> 4) * 128;
            // d_hat in place; per-row local mins -> atomicMin
            #pragma unroll
            for (int mi = 0; mi < 4; mi++) {
                float mlo = 3.0e38f, mhi = 3.0e38f;
                #pragma unroll
                for (int ni = 0; ni < 4; ni++) {
                    int col = nt + wn * 32 + ni * 8 + 2 * lq;
                    float cc0 = __ldg(&g_cc[col]);
                    float cc1 = __ldg(&g_cc[col + 1]);
                    acc[mi][ni][0] = cc0 - 2.0f * acc[mi][ni][0];
                    acc[mi][ni][1] = cc1 - 2.0f * acc[mi][ni][1];
                    acc[mi][ni][2] = cc0 - 2.0f * acc[mi][ni][2];
                    acc[mi][ni][3] = cc1 - 2.0f * acc[mi][ni][3];
                    mlo = fminf(mlo, fminf(acc[mi][ni][0], acc[mi][ni][1]));
                    mhi = fminf(mhi, fminf(acc[mi][ni][2], acc[mi][ni][3]));
                }
                int rl = wm * 64 + mi * 16 + lr;
                atomicMin(&s_min[rl],     ordkey(mlo));
                atomicMin(&s_min[rl + 8], ordkey(mhi));
            }
            __syncthreads();                   // tile's mins visible
            #pragma unroll
            for (int mi = 0; mi < 4; mi++) {
                int rl = wm * 64 + mi * 16 + lr;
                float thr_lo = orddec(s_min[rl]) + MARGIN;
                float thr_hi = orddec(s_min[rl + 8]) + MARGIN;
                #pragma unroll
                for (int ni = 0; ni < 4; ni++) {
                    int col = nt + wn * 32 + ni * 8 + 2 * lq;
                    #pragma unroll
                    for (int v = 0; v < 4; v++) {
                        float d = acc[mi][ni][v];
                        int r = (v < 2) ? rl : rl + 8;
                        float thr = (v < 2) ? thr_lo : thr_hi;
                        if (d <= thr) {
                            int pos = atomicAdd(&s_cnt[r], 1);
                            if (pos < CAP) s_cols[r][pos] = (uint16_t)(col + (v & 1));
                        }
                        acc[mi][ni][v] = 0.0f;
                    }
                }
            }
        }
    }

    // ---- exact fp32 rescue: 16 rows per warp ----
    __syncthreads();
    for (int rr = 0; rr < 16; rr++) {
        int r = wid * 16 + rr;
        int grow = r0 + r;
        int cnt = s_cnt[r];
        float xr[16];
        #pragma unroll
        for (int q = 0; q < 16; q++)
            xr[q] = g_xT[(size_t)grow * Cdim + lane + q * 32];
        float bestE = 3.0e38f;
        int   bestI = 0x7fffffff;
        if (cnt <= CAP) {
            for (int c = 0; c < cnt; c++) {
                int j = s_cols[r][c];
                const float* crow = cb + (size_t)j * Cdim;
                float p = 0.0f;
                #pragma unroll
                for (int q = 0; q < 16; q++)
                    p += xr[q] * __ldg(&crow[lane + q * 32]);
                #pragma unroll
                for (int o = 16; o > 0; o >>= 1) p += __shfl_xor_sync(0xffffffffu, p, o);
                float d = __ldg(&g_cc[j]) - 2.0f * p;
                if (d < bestE || (d == bestE && j < bestI)) { bestE = d; bestI = j; }
            }
        } else {
            // overflow fallback (essentially never): exact scan of all codes
            for (int j = 0; j < NB; j++) {
                const float* crow = cb + (size_t)j * Cdim;
                float p = 0.0f;
                #pragma unroll
                for (int q = 0; q < 16; q++)
                    p += xr[q] * __ldg(&crow[lane + q * 32]);
                #pragma unroll
                for (int o = 16; o > 0; o >>= 1) p += __shfl_xor_sync(0xffffffffu, p, o);
                float d = __ldg(&g_cc[j]) - 2.0f * p;
                if (d < bestE) { bestE = d; bestI = j; }
            }
        }
        if (lane == 0) g_idx[grow] = bestI;
    }
}

// ---------------- 4: segment sum scatter + counts ----------------
__global__ void scatter_kernel(const float* __restrict__ x) {
    int gi = (blockIdx.x * 256 + threadIdx.x) << 2;
    int n = gi >> 19;
    int rem = gi & (CT - 1);
    int c = rem >> 10;
    int t = rem & 1023;
    int row = (n << 10) + t;
    float4 xv = *(const float4*)(x + gi);
    int4 idx = *(const int4*)(g_idx + row);
    atomicAdd(&g_nsum[idx.x * Cdim + c], xv.x);
    atomicAdd(&g_nsum[idx.y * Cdim + c], xv.y);
    atomicAdd(&g_nsum[idx.z * Cdim + c], xv.z);
    atomicAdd(&g_nsum[idx.w * Cdim + c], xv.w);
    if (c == 0) {
        atomicAdd(&g_ncnt[idx.x], 1.0f);
        atomicAdd(&g_ncnt[idx.y], 1.0f);
        atomicAdd(&g_ncnt[idx.z], 1.0f);
        atomicAdd(&g_ncnt[idx.w], 1.0f);
    }
}

// ---------------- 5: x_d output + commit-loss partial ----------------
__global__ void out_kernel(const float* __restrict__ x, const float* __restrict__ cb,
                           float* __restrict__ out) {
    int gi = (blockIdx.x * 256 + threadIdx.x) << 2;
    int n = gi >> 19;
    int rem = gi & (CT - 1);
    int c = rem >> 10;
    int t = rem & 1023;
    int row = (n << 10) + t;
    float4 xv = *(const float4*)(x + gi);
    int4 idx = *(const int4*)(g_idx + row);
    float4 o;
    o.x = cb[(size_t)idx.x * Cdim + c];
    o.y = cb[(size_t)idx.y * Cdim + c];
    o.z = cb[(size_t)idx.z * Cdim + c];
    o.w = cb[(size_t)idx.w * Cdim + c];
    *(float4*)(out + OFF_XD + gi) = o;
    float dx = xv.x - o.x, dy = xv.y - o.y, dz = xv.z - o.z, dw = xv.w - o.w;
    float s = dx * dx + dy * dy + dz * dz + dw * dw;
    #pragma unroll
    for (int off = 16; off > 0; off >>= 1) s += __shfl_xor_sync(0xffffffffu, s, off);
    __shared__ float sh[8];
    int lane = threadIdx.x & 31, w = threadIdx.x >> 5;
    if (lane == 0) sh[w] = s;
    __syncthreads();
    if (threadIdx.x == 0) {
        float tot = 0.0f;
        #pragma unroll
        for (int i = 0; i < 8; i++) tot += sh[i];
        atomicAdd(&g_loss, tot);
    }
}

// ---------------- 6: EMA update + codebook reset + count out ----------------
__global__ void ema_kernel(const float* __restrict__ x,
                           const float* __restrict__ code_sum,
                           const float* __restrict__ code_count,
                           float* __restrict__ out) {
    int gi = blockIdx.x * 256 + threadIdx.x;
    int code = gi >> 9;
    int c = gi & 511;
    float cse = 0.99f * code_sum[gi] + 0.01f * g_nsum[gi];
    float cnt = 0.99f * code_count[code] + 0.01f * g_ncnt[code];
    out[OFF_CSE + gi] = cse;
    float ncb;
    if (cnt >= 1.0f) {
        ncb = cse / fmaxf(cnt, 1e-10f);
    } else {
        int t = code & 1023;
        int n = code >> 10;
        ncb = x[(size_t)n * CT + (size_t)c * Tdim + t];
    }
    out[OFF_CB + gi] = ncb;
    if (c == 0) out[OFF_CNT + code] = cnt;
}

// ---------------- 7: perplexity + loss finalize ----------------
__global__ void finalize_kernel(float* __restrict__ out) {
    float h = 0.0f;
    for (int code = threadIdx.x; code < NB; code += 256) {
        float p = g_ncnt[code] * (1.0f / 32768.0f);
        h += p * logf(p + 1e-7f);
    }
    #pragma unroll
    for (int off = 16; off > 0; off >>= 1) h += __shfl_xor_sync(0xffffffffu, h, off);
    __shared__ float sh[8];
    int lane = threadIdx.x & 31, w = threadIdx.x >> 5;
    if (lane == 0) sh[w] = h;
    __syncthreads();
    if (threadIdx.x == 0) {
        float tot = 0.0f;
        #pragma unroll
        for (int i = 0; i < 8; i++) tot += sh[i];
        out[OFF_PERP] = expf(-tot);
        out[OFF_LOSS] = g_loss * (1.0f / (float)XSZ);
    }
}

extern "C" void kernel_launch(void* const* d_in, const int* in_sizes, int n_in,
                              void* d_out, int out_size) {
    const float* x    = (const float*)d_in[0];
    const float* cb   = (const float*)d_in[1];
    const float* csum = (const float*)d_in[2];
    const float* ccnt = (const float*)d_in[3];
    float* out = (float*)d_out;

    cudaFuncSetAttribute(gemm_argmin, cudaFuncAttributeMaxDynamicSharedMemorySize, SMEM_BYTES);

    zero_kernel     <<<(NB * Cdim + 255) / 256, 256>>>();
    norms_kernel    <<<NB / 8, 256>>>(cb);
    transpose_kernel<<<Ndim * 32 * 16, 256>>>(x);
    gemm_argmin     <<<NT / BM, 256, SMEM_BYTES>>>(x, cb);
    scatter_kernel  <<<XSZ / 4 / 256, 256>>>(x);
    out_kernel      <<<XSZ / 4 / 256, 256>>>(x, cb, out);
    ema_kernel      <<<NB * Cdim / 256, 256>>>(x, csum, ccnt, out);
    finalize_kernel <<<1, 256>>>(out);
}

// round 7
// speedup vs baseline: 1.0118x; 1.0118x over previous
#include <cuda_runtime.h>
#include <math.h>
#include <cstdint>

#define Ndim 32
#define Cdim 512
#define Tdim 1024
#define NT   32768
#define NB   2048
#define CT   (Cdim*Tdim)
#define XSZ  (Ndim*Cdim*Tdim)

#define OFF_XD   0
#define OFF_LOSS 16777216
#define OFF_PERP 16777217
#define OFF_CB   16777218
#define OFF_CSE  (OFF_CB + NB*Cdim)
#define OFF_CNT  (OFF_CSE + NB*Cdim)

// Scratch (device globals: the sanctioned no-cudaMalloc path)
__device__ __align__(16) float g_cc[NB];
__device__ __align__(16) int   g_idx[NT];
__device__ __align__(16) float g_nsum[NB*Cdim];
__device__ __align__(16) float g_ncnt[NB];
__device__ float g_loss;
__device__ __align__(16) float g_xT[(size_t)NT * Cdim];   // 64 MB x transposed [row][c]

// ---------------------------------------------------------------- helpers
__device__ __forceinline__ void cp_async16(uint32_t saddr, const void* g) {
    asm volatile("cp.async.ca.shared.global [%0], [%1], 16;" :: "r"(saddr), "l"(g));
}
__device__ __forceinline__ void cp_commit() {
    asm volatile("cp.async.commit_group;" ::: "memory");
}
__device__ __forceinline__ void mma_tf32(float* d, const uint32_t* a, const uint32_t* b) {
    asm volatile(
        "mma.sync.aligned.m16n8k8.row.col.f32.tf32.tf32.f32 "
        "{%0,%1,%2,%3}, {%4,%5,%6,%7}, {%8,%9}, {%0,%1,%2,%3};"
        : "+f"(d[0]), "+f"(d[1]), "+f"(d[2]), "+f"(d[3])
        : "r"(a[0]), "r"(a[1]), "r"(a[2]), "r"(a[3]), "r"(b[0]), "r"(b[1]));
}
// monotonic float<->uint key (ascending)
__device__ __forceinline__ uint32_t ordkey(float f) {
    uint32_t u = __float_as_uint(f);
    return (u >> 31) ? ~u : (u | 0x80000000u);
}
__device__ __forceinline__ float orddec(uint32_t k) {
    uint32_t u = (k & 0x80000000u) ? (k & 0x7fffffffu) : ~k;
    return __uint_as_float(u);
}

// ---------------- 0: zero scratch ----------------
__global__ void zero_kernel() {
    int i = blockIdx.x * 256 + threadIdx.x;
    if (i < NB * Cdim) g_nsum[i] = 0.0f;
    if (i < NB)        g_ncnt[i] = 0.0f;
    if (i == 0)        g_loss = 0.0f;
}

// ---------------- 1: codebook squared norms ----------------
__global__ void norms_kernel(const float* __restrict__ cb) {
    int warp = threadIdx.x >> 5, lane = threadIdx.x & 31;
    int code = blockIdx.x * 8 + warp;
    const float* row = cb + (size_t)code * Cdim;
    float s = 0.0f;
    for (int j = lane; j < Cdim; j += 32) { float v = row[j]; s += v * v; }
    #pragma unroll
    for (int o = 16; o > 0; o >>= 1) s += __shfl_xor_sync(0xffffffffu, s, o);
    if (lane == 0) g_cc[code] = s;
}

// ---------------- 2: transpose x -> xT[row][c] ----------------
__global__ void transpose_kernel(const float* __restrict__ x) {
    __shared__ float s[32][33];
    int b = blockIdx.x;
    int ct = b & 15;
    int tt = (b >> 4) & 31;
    int n  = b >> 9;
    int tid = threadIdx.x;
    int l5 = tid & 31, h3 = tid >> 5;
    #pragma unroll
    for (int q = 0; q < 4; q++) {
        int c_l = h3 + q * 8;
        s[c_l][l5] = x[(size_t)n * CT + (size_t)(ct * 32 + c_l) * Tdim + tt * 32 + l5];
    }
    __syncthreads();
    #pragma unroll
    for (int q = 0; q < 4; q++) {
        int t_l = h3 + q * 8;
        g_xT[(size_t)(n * 1024 + tt * 32 + t_l) * Cdim + ct * 32 + l5] = s[l5][t_l];
    }
}

// ---------------- 3: fused TF32 screen GEMM + candidate argmin + exact rescue ----------------
// Main loop is byte-identical to the 587us/38.6%-tensor Round-5 structure
// (2-stage cp.async, prefetch-before-wait, wait_group 1, two syncs/iter).
// Only the (i&15)==15 epilogue differs: screening instead of d_hat spill.
#define BM 128
#define BN 128
#define BK 32
#define AS_STRIDE 136
#define BS_STRIDE 36
#define AS_FLOATS (BK * AS_STRIDE)                 // 4352
#define BS_FLOATS (BN * BS_STRIDE)                 // 4608
#define SMEM_BYTES ((2*AS_FLOATS + 2*BS_FLOATS)*4) // 71680
#define CAP 16
#define MARGIN 8.0f

__global__ __launch_bounds__(256, 2) void gemm_argmin(const float* __restrict__ x,
                                                      const float* __restrict__ cb) {
    extern __shared__ float sm[];
    __shared__ uint32_t s_min[128];
    __shared__ int      s_cnt[128];
    __shared__ uint16_t s_cols[128][CAP];

    float* As[2] = { sm, sm + AS_FLOATS };
    float* Bs[2] = { sm + 2*AS_FLOATS, sm + 2*AS_FLOATS + BS_FLOATS };
    uint32_t smbase = (uint32_t)__cvta_generic_to_shared(sm);
    uint32_t smA[2] = { smbase, smbase + AS_FLOATS*4u };
    uint32_t smB[2] = { smbase + 2u*AS_FLOATS*4u, smbase + (2u*AS_FLOATS + BS_FLOATS)*4u };

    int tid = threadIdx.x, lane = tid & 31, wid = tid >> 5;
    int wm = wid >> 2, wn = wid & 3;       // warp grid 2 (m) x 4 (n)
    int lq = lane & 3, lr = lane >> 2;
    int r0 = blockIdx.x * BM;
    const float* xb = x + (size_t)(r0 >> 10) * CT + (r0 & 1023);

    int a_p  = (tid & 31) << 2;
    int a_kb = tid >> 5;
    int b_kp = (tid & 7) << 2;
    int b_cb = tid >> 3;

    if (tid < 128) { s_min[tid] = 0xFFFFFFFFu; s_cnt[tid] = 0; }

    float acc[4][4][4];
    #pragma unroll
    for (int mi = 0; mi < 4; mi++)
        #pragma unroll
        for (int ni = 0; ni < 4; ni++)
            #pragma unroll
            for (int v = 0; v < 4; v++) acc[mi][ni][v] = 0.0f;

    auto load_tiles = [&](int buf, int nt, int kc) {
        #pragma unroll
        for (int it = 0; it < 4; it++) {
            int k = a_kb + it * 8;
            cp_async16(smA[buf] + (uint32_t)(k * AS_STRIDE + a_p) * 4u,
                       xb + (size_t)(kc + k) * Tdim + a_p);
        }
        #pragma unroll
        for (int it = 0; it < 4; it++) {
            int code = b_cb + it * 32;
            cp_async16(smB[buf] + (uint32_t)(code * BS_STRIDE + b_kp) * 4u,
                       cb + (size_t)(nt + code) * Cdim + kc + b_kp);
        }
        cp_commit();
    };

    load_tiles(0, 0, 0);

    for (int i = 0; i < 256; i++) {            // (nt, kc) flattened: 16 x 16
        int nxt = i + 1;
        if (nxt < 256) {
            load_tiles(nxt & 1, (nxt >> 4) * 128, (nxt & 15) * 32);
            asm volatile("cp.async.wait_group 1;" ::: "memory");
        } else {
            asm volatile("cp.async.wait_group 0;" ::: "memory");
        }
        __syncthreads();

        const float* A = As[i & 1];
        const float* B = Bs[i & 1];
        #pragma unroll
        for (int kk = 0; kk < 4; kk++) {
            uint32_t a[4][4], b[4][2];
            #pragma unroll
            for (int mi = 0; mi < 4; mi++) {
                const float* ap = A + (kk * 8 + lq) * AS_STRIDE + wm * 64 + mi * 16 + lr;
                a[mi][0] = __float_as_uint(ap[0]);
                a[mi][1] = __float_as_uint(ap[8]);
                a[mi][2] = __float_as_uint(ap[4 * AS_STRIDE]);
                a[mi][3] = __float_as_uint(ap[4 * AS_STRIDE + 8]);
            }
            #pragma unroll
            for (int ni = 0; ni < 4; ni++) {
                const float* bp = B + (wn * 32 + ni * 8 + lr) * BS_STRIDE + kk * 8 + lq;
                b[ni][0] = __float_as_uint(bp[0]);
                b[ni][1] = __float_as_uint(bp[4]);
            }
            #pragma unroll
            for (int mi = 0; mi < 4; mi++)
                #pragma unroll
                for (int ni = 0; ni < 4; ni++)
                    mma_tf32(acc[mi][ni], a[mi], b[ni]);
        }

        if ((i & 15) == 15) {                  // end of K: screen this n-tile
            int nt = (i >> 4) * 128;
            #pragma unroll
            for (int mi = 0; mi < 4; mi++) {
                float mlo = 3.0e38f, mhi = 3.0e38f;
                #pragma unroll
                for (int ni = 0; ni < 4; ni++) {
                    int col = nt + wn * 32 + ni * 8 + 2 * lq;
                    float cc0 = __ldg(&g_cc[col]);
                    float cc1 = __ldg(&g_cc[col + 1]);
                    acc[mi][ni][0] = cc0 - 2.0f * acc[mi][ni][0];
                    acc[mi][ni][1] = cc1 - 2.0f * acc[mi][ni][1];
                    acc[mi][ni][2] = cc0 - 2.0f * acc[mi][ni][2];
                    acc[mi][ni][3] = cc1 - 2.0f * acc[mi][ni][3];
                    mlo = fminf(mlo, fminf(acc[mi][ni][0], acc[mi][ni][1]));
                    mhi = fminf(mhi, fminf(acc[mi][ni][2], acc[mi][ni][3]));
                }
                int rl = wm * 64 + mi * 16 + lr;
                atomicMin(&s_min[rl],     ordkey(mlo));
                atomicMin(&s_min[rl + 8], ordkey(mhi));
            }
            __syncthreads();                   // tile's mins visible
            #pragma unroll
            for (int mi = 0; mi < 4; mi++) {
                int rl = wm * 64 + mi * 16 + lr;
                float thr_lo = orddec(s_min[rl]) + MARGIN;
                float thr_hi = orddec(s_min[rl + 8]) + MARGIN;
                #pragma unroll
                for (int ni = 0; ni < 4; ni++) {
                    int col = nt + wn * 32 + ni * 8 + 2 * lq;
                    #pragma unroll
                    for (int v = 0; v < 4; v++) {
                        float d = acc[mi][ni][v];
                        int r = (v < 2) ? rl : rl + 8;
                        float thr = (v < 2) ? thr_lo : thr_hi;
                        if (d <= thr) {
                            int pos = atomicAdd(&s_cnt[r], 1);
                            if (pos < CAP) s_cols[r][pos] = (uint16_t)(col + (v & 1));
                        }
                        acc[mi][ni][v] = 0.0f;
                    }
                }
            }
        }
        __syncthreads();
    }

    // ---- exact fp32 rescue: 16 rows per warp ----
    for (int rr = 0; rr < 16; rr++) {
        int r = wid * 16 + rr;
        int grow = r0 + r;
        int cnt = s_cnt[r];
        float xr[16];
        #pragma unroll
        for (int q = 0; q < 16; q++)
            xr[q] = g_xT[(size_t)grow * Cdim + lane + q * 32];
        float bestE = 3.0e38f;
        int   bestI = 0x7fffffff;
        if (cnt <= CAP) {
            for (int c = 0; c < cnt; c++) {
                int j = s_cols[r][c];
                const float* crow = cb + (size_t)j * Cdim;
                float p = 0.0f;
                #pragma unroll
                for (int q = 0; q < 16; q++)
                    p += xr[q] * __ldg(&crow[lane + q * 32]);
                #pragma unroll
                for (int o = 16; o > 0; o >>= 1) p += __shfl_xor_sync(0xffffffffu, p, o);
                float d = __ldg(&g_cc[j]) - 2.0f * p;
                if (d < bestE || (d == bestE && j < bestI)) { bestE = d; bestI = j; }
            }
        } else {
            // overflow fallback (essentially never): exact scan of all codes
            for (int j = 0; j < NB; j++) {
                const float* crow = cb + (size_t)j * Cdim;
                float p = 0.0f;
                #pragma unroll
                for (int q = 0; q < 16; q++)
                    p += xr[q] * __ldg(&crow[lane + q * 32]);
                #pragma unroll
                for (int o = 16; o > 0; o >>= 1) p += __shfl_xor_sync(0xffffffffu, p, o);
                float d = __ldg(&g_cc[j]) - 2.0f * p;
                if (d < bestE) { bestE = d; bestI = j; }
            }
        }
        if (lane == 0) g_idx[grow] = bestI;
    }
}

// ---------------- 4: fused scatter (segment sums + counts) + x_d output + loss ----------------
__global__ void scatter_out_kernel(const float* __restrict__ x, const float* __restrict__ cb,
                                   float* __restrict__ out) {
    int gi = (blockIdx.x * 256 + threadIdx.x) << 2;
    int n = gi >> 19;
    int rem = gi & (CT - 1);
    int c = rem >> 10;
    int t = rem & 1023;
    int row = (n << 10) + t;
    float4 xv = *(const float4*)(x + gi);
    int4 idx = *(const int4*)(g_idx + row);

    // segment sums (+ counts from the c==0 slice)
    atomicAdd(&g_nsum[idx.x * Cdim + c], xv.x);
    atomicAdd(&g_nsum[idx.y * Cdim + c], xv.y);
    atomicAdd(&g_nsum[idx.z * Cdim + c], xv.z);
    atomicAdd(&g_nsum[idx.w * Cdim + c], xv.w);
    if (c == 0) {
        atomicAdd(&g_ncnt[idx.x], 1.0f);
        atomicAdd(&g_ncnt[idx.y], 1.0f);
        atomicAdd(&g_ncnt[idx.z], 1.0f);
        atomicAdd(&g_ncnt[idx.w], 1.0f);
    }

    // x_d gather + write + commit loss partial
    float4 o;
    o.x = cb[(size_t)idx.x * Cdim + c];
    o.y = cb[(size_t)idx.y * Cdim + c];
    o.z = cb[(size_t)idx.z * Cdim + c];
    o.w = cb[(size_t)idx.w * Cdim + c];
    *(float4*)(out + OFF_XD + gi) = o;
    float dx = xv.x - o.x, dy = xv.y - o.y, dz = xv.z - o.z, dw = xv.w - o.w;
    float s = dx * dx + dy * dy + dz * dz + dw * dw;
    #pragma unroll
    for (int off = 16; off > 0; off >>= 1) s += __shfl_xor_sync(0xffffffffu, s, off);
    __shared__ float sh[8];
    int lane = threadIdx.x & 31, w = threadIdx.x >> 5;
    if (lane == 0) sh[w] = s;
    __syncthreads();
    if (threadIdx.x == 0) {
        float tot = 0.0f;
        #pragma unroll
        for (int i = 0; i < 8; i++) tot += sh[i];
        atomicAdd(&g_loss, tot);
    }
}

// ---------------- 5: EMA update + codebook reset + count out ----------------
__global__ void ema_kernel(const float* __restrict__ x,
                           const float* __restrict__ code_sum,
                           const float* __restrict__ code_count,
                           float* __restrict__ out) {
    int gi = blockIdx.x * 256 + threadIdx.x;
    int code = gi >> 9;
    int c = gi & 511;
    float cse = 0.99f * code_sum[gi] + 0.01f * g_nsum[gi];
    float cnt = 0.99f * code_count[code] + 0.01f * g_ncnt[code];
    out[OFF_CSE + gi] = cse;
    float ncb;
    if (cnt >= 1.0f) {
        ncb = cse / fmaxf(cnt, 1e-10f);
    } else {
        int t = code & 1023;
        int n = code >> 10;
        ncb = x[(size_t)n * CT + (size_t)c * Tdim + t];
    }
    out[OFF_CB + gi] = ncb;
    if (c == 0) out[OFF_CNT + code] = cnt;
}

// ---------------- 6: perplexity + loss finalize ----------------
__global__ void finalize_kernel(float* __restrict__ out) {
    float h = 0.0f;
    for (int code = threadIdx.x; code < NB; code += 256) {
        float p = g_ncnt[code] * (1.0f / 32768.0f);
        h += p * logf(p + 1e-7f);
    }
    #pragma unroll
    for (int off = 16; off > 0; off >>= 1) h += __shfl_xor_sync(0xffffffffu, h, off);
    __shared__ float sh[8];
    int lane = threadIdx.x & 31, w = threadIdx.x >> 5;
    if (lane == 0) sh[w] = h;
    __syncthreads();
    if (threadIdx.x == 0) {
        float tot = 0.0f;
        #pragma unroll
        for (int i = 0; i < 8; i++) tot += sh[i];
        out[OFF_PERP] = expf(-tot);
        out[OFF_LOSS] = g_loss * (1.0f / (float)XSZ);
    }
}

extern "C" void kernel_launch(void* const* d_in, const int* in_sizes, int n_in,
                              void* d_out, int out_size) {
    const float* x    = (const float*)d_in[0];
    const float* cb   = (const float*)d_in[1];
    const float* csum = (const float*)d_in[2];
    const float* ccnt = (const float*)d_in[3];
    float* out = (float*)d_out;

    cudaFuncSetAttribute(gemm_argmin, cudaFuncAttributeMaxDynamicSharedMemorySize, SMEM_BYTES);

    zero_kernel      <<<(NB * Cdim + 255) / 256, 256>>>();
    norms_kernel     <<<NB / 8, 256>>>(cb);
    transpose_kernel <<<Ndim * 32 * 16, 256>>>(x);
    gemm_argmin      <<<NT / BM, 256, SMEM_BYTES>>>(x, cb);
    scatter_out_kernel<<<XSZ / 4 / 256, 256>>>(x, cb, out);
    ema_kernel       <<<NB * Cdim / 256, 256>>>(x, csum, ccnt, out);
    finalize_kernel  <<<1, 256>>>(out);
}

// round 8
// speedup vs baseline: 1.2874x; 1.2724x over previous
#include <cuda_runtime.h>
#include <math.h>
#include <cstdint>

#define Ndim 32
#define Cdim 512
#define Tdim 1024
#define NT   32768
#define NB   2048
#define CT   (Cdim*Tdim)
#define XSZ  (Ndim*Cdim*Tdim)

#define OFF_XD   0
#define OFF_LOSS 16777216
#define OFF_PERP 16777217
#define OFF_CB   16777218
#define OFF_CSE  (OFF_CB + NB*Cdim)
#define OFF_CNT  (OFF_CSE + NB*Cdim)

// Scratch (device globals: the sanctioned no-cudaMalloc path)
__device__ __align__(16) float g_cc[NB];
__device__ __align__(16) int   g_idx[NT];
__device__ __align__(16) float g_nsum[NB*Cdim];
__device__ __align__(16) float g_ncnt[NB];
__device__ float g_loss;
__device__ __align__(16) float g_dhat[(size_t)NT * NB];   // 256 MB approx distances
__device__ __align__(16) float g_xT[(size_t)NT * Cdim];   // 64 MB x transposed [row][c]

// ---------------------------------------------------------------- helpers
__device__ __forceinline__ void cp_async16(uint32_t saddr, const void* g) {
    asm volatile("cp.async.ca.shared.global [%0], [%1], 16;" :: "r"(saddr), "l"(g));
}
__device__ __forceinline__ void cp_commit() {
    asm volatile("cp.async.commit_group;" ::: "memory");
}
__device__ __forceinline__ void mma_tf32(float* d, const uint32_t* a, const uint32_t* b) {
    asm volatile(
        "mma.sync.aligned.m16n8k8.row.col.f32.tf32.tf32.f32 "
        "{%0,%1,%2,%3}, {%4,%5,%6,%7}, {%8,%9}, {%0,%1,%2,%3};"
        : "+f"(d[0]), "+f"(d[1]), "+f"(d[2]), "+f"(d[3])
        : "r"(a[0]), "r"(a[1]), "r"(a[2]), "r"(a[3]), "r"(b[0]), "r"(b[1]));
}

// ---------------- 0: zero scratch ----------------
__global__ void zero_kernel() {
    int i = blockIdx.x * 256 + threadIdx.x;
    if (i < NB * Cdim) g_nsum[i] = 0.0f;
    if (i < NB)        g_ncnt[i] = 0.0f;
    if (i == 0)        g_loss = 0.0f;
}

// ---------------- 1: codebook squared norms ----------------
__global__ void norms_kernel(const float* __restrict__ cb) {
    int warp = threadIdx.x >> 5, lane = threadIdx.x & 31;
    int code = blockIdx.x * 8 + warp;
    const float* row = cb + (size_t)code * Cdim;
    float s = 0.0f;
    for (int j = lane; j < Cdim; j += 32) { float v = row[j]; s += v * v; }
    #pragma unroll
    for (int o = 16; o > 0; o >>= 1) s += __shfl_xor_sync(0xffffffffu, s, o);
    if (lane == 0) g_cc[code] = s;
}

// ---------------- 2: transpose x -> xT[row][c] ----------------
__global__ void transpose_kernel(const float* __restrict__ x) {
    __shared__ float s[32][33];
    int b = blockIdx.x;
    int ct = b & 15;          // c tile (16)
    int tt = (b >> 4) & 31;   // t tile (32)
    int n  = b >> 9;          // batch (32)
    int tid = threadIdx.x;
    int l5 = tid & 31, h3 = tid >> 5;
    #pragma unroll
    for (int q = 0; q < 4; q++) {
        int c_l = h3 + q * 8;
        s[c_l][l5] = x[(size_t)n * CT + (size_t)(ct * 32 + c_l) * Tdim + tt * 32 + l5];
    }
    __syncthreads();
    #pragma unroll
    for (int q = 0; q < 4; q++) {
        int t_l = h3 + q * 8;
        g_xT[(size_t)(n * 1024 + tt * 32 + t_l) * Cdim + ct * 32 + l5] = s[l5][t_l];
    }
}

// ---------------- 3: TF32 mma.sync screen GEMM -> d_hat ----------------
// BM=128 rows x all 2048 codes (16 n-tiles of 128), BK=32, double-buffered cp.async.
// VERBATIM Round-5 binary-proven structure (587.8us / 38.6% tensor) — do not edit.
#define BM 128
#define BN 128
#define BK 32
#define AS_STRIDE 136
#define BS_STRIDE 36
#define AS_FLOATS (BK * AS_STRIDE)                 // 4352
#define BS_FLOATS (BN * BS_STRIDE)                 // 4608
#define SMEM_BYTES ((2*AS_FLOATS + 2*BS_FLOATS)*4) // 71680

__global__ __launch_bounds__(256, 2) void gemm_dhat(const float* __restrict__ x,
                                                    const float* __restrict__ cb) {
    extern __shared__ float sm[];
    float* As[2] = { sm, sm + AS_FLOATS };
    float* Bs[2] = { sm + 2*AS_FLOATS, sm + 2*AS_FLOATS + BS_FLOATS };
    uint32_t smbase = (uint32_t)__cvta_generic_to_shared(sm);
    uint32_t smA[2] = { smbase, smbase + AS_FLOATS*4u };
    uint32_t smB[2] = { smbase + 2u*AS_FLOATS*4u, smbase + (2u*AS_FLOATS + BS_FLOATS)*4u };

    int tid = threadIdx.x, lane = tid & 31, wid = tid >> 5;
    int wm = wid >> 2, wn = wid & 3;       // warp grid 2 (m) x 4 (n)
    int lq = lane & 3, lr = lane >> 2;
    int r0 = blockIdx.x * BM;
    const float* xb = x + (size_t)(r0 >> 10) * CT + (r0 & 1023);

    int a_p  = (tid & 31) << 2;  // float offset within a k-row (0..124)
    int a_kb = tid >> 5;         // base k (0..7)
    int b_kp = (tid & 7) << 2;   // float offset within code row
    int b_cb = tid >> 3;         // base code (0..31)

    float acc[4][4][4];
    #pragma unroll
    for (int mi = 0; mi < 4; mi++)
        #pragma unroll
        for (int ni = 0; ni < 4; ni++)
            #pragma unroll
            for (int v = 0; v < 4; v++) acc[mi][ni][v] = 0.0f;

    auto load_tiles = [&](int buf, int nt, int kc) {
        #pragma unroll
        for (int it = 0; it < 4; it++) {
            int k = a_kb + it * 8;
            cp_async16(smA[buf] + (uint32_t)(k * AS_STRIDE + a_p) * 4u,
                       xb + (size_t)(kc + k) * Tdim + a_p);
        }
        #pragma unroll
        for (int it = 0; it < 4; it++) {
            int code = b_cb + it * 32;
            cp_async16(smB[buf] + (uint32_t)(code * BS_STRIDE + b_kp) * 4u,
                       cb + (size_t)(nt + code) * Cdim + kc + b_kp);
        }
        cp_commit();
    };

    load_tiles(0, 0, 0);

    for (int i = 0; i < 256; i++) {            // (nt, kc) flattened: 16 x 16
        int nxt = i + 1;
        if (nxt < 256) {
            load_tiles(nxt & 1, (nxt >> 4) * 128, (nxt & 15) * 32);
            asm volatile("cp.async.wait_group 1;" ::: "memory");
        } else {
            asm volatile("cp.async.wait_group 0;" ::: "memory");
        }
        __syncthreads();

        const float* A = As[i & 1];
        const float* B = Bs[i & 1];
        #pragma unroll
        for (int kk = 0; kk < 4; kk++) {
            uint32_t a[4][4], b[4][2];
            #pragma unroll
            for (int mi = 0; mi < 4; mi++) {
                const float* ap = A + (kk * 8 + lq) * AS_STRIDE + wm * 64 + mi * 16 + lr;
                a[mi][0] = __float_as_uint(ap[0]);
                a[mi][1] = __float_as_uint(ap[8]);
                a[mi][2] = __float_as_uint(ap[4 * AS_STRIDE]);
                a[mi][3] = __float_as_uint(ap[4 * AS_STRIDE + 8]);
            }
            #pragma unroll
            for (int ni = 0; ni < 4; ni++) {
                const float* bp = B + (wn * 32 + ni * 8 + lr) * BS_STRIDE + kk * 8 + lq;
                b[ni][0] = __float_as_uint(bp[0]);
                b[ni][1] = __float_as_uint(bp[4]);
            }
            #pragma unroll
            for (int mi = 0; mi < 4; mi++)
                #pragma unroll
                for (int ni = 0; ni < 4; ni++)
                    mma_tf32(acc[mi][ni], a[mi], b[ni]);
        }

        if ((i & 15) == 15) {  // end of K for this n-tile: spill d_hat, reset accs
            int nt = (i >> 4) * 128;
            #pragma unroll
            for (int mi = 0; mi < 4; mi++) {
                int row = r0 + wm * 64 + mi * 16 + lr;
                #pragma unroll
                for (int ni = 0; ni < 4; ni++) {
                    int col = nt + wn * 32 + ni * 8 + 2 * lq;
                    float cc0 = __ldg(&g_cc[col]);
                    float cc1 = __ldg(&g_cc[col + 1]);
                    float2 v0 = make_float2(cc0 - 2.0f * acc[mi][ni][0],
                                            cc1 - 2.0f * acc[mi][ni][1]);
                    float2 v1 = make_float2(cc0 - 2.0f * acc[mi][ni][2],
                                            cc1 - 2.0f * acc[mi][ni][3]);
                    *(float2*)&g_dhat[(size_t)row * NB + col] = v0;
                    *(float2*)&g_dhat[(size_t)(row + 8) * NB + col] = v1;
                    acc[mi][ni][0] = acc[mi][ni][1] = acc[mi][ni][2] = acc[mi][ni][3] = 0.0f;
                }
            }
        }
        __syncthreads();
    }
}

// ---------------- 4: rescue — exact fp32 argmin among margin candidates ----------------
// Margin 8.0 > 2*delta, delta <= 2^-9 * |x||c| (tf32 truncation worst case).
__global__ void rescue_kernel(const float* __restrict__ cb) {
    int wid = threadIdx.x >> 5, lane = threadIdx.x & 31;
    int row = blockIdx.x * 8 + wid;

    float xr[16];
    #pragma unroll
    for (int q = 0; q < 16; q++)
        xr[q] = g_xT[(size_t)row * Cdim + lane + q * 32];

    float dv[64];
    const float* drow = &g_dhat[(size_t)row * NB];
    #pragma unroll
    for (int i = 0; i < 64; i++) dv[i] = drow[lane + i * 32];

    float bv = dv[0];
    #pragma unroll
    for (int i = 1; i < 64; i++) bv = fminf(bv, dv[i]);
    #pragma unroll
    for (int o = 16; o > 0; o >>= 1) bv = fminf(bv, __shfl_xor_sync(0xffffffffu, bv, o));

    float thr = bv + 8.0f;
    float bestE = 3.0e38f;
    int   bestI = 0;
    #pragma unroll 4
    for (int i = 0; i < 64; i++) {
        unsigned mask = __ballot_sync(0xffffffffu, dv[i] <= thr);
        while (mask) {
            int s = __ffs(mask) - 1;
            mask &= mask - 1;
            int j = i * 32 + s;
            const float* crow = cb + (size_t)j * Cdim;
            float p = 0.0f;
            #pragma unroll
            for (int q = 0; q < 16; q++)
                p += xr[q] * __ldg(&crow[lane + q * 32]);
            #pragma unroll
            for (int o = 16; o > 0; o >>= 1) p += __shfl_xor_sync(0xffffffffu, p, o);
            float d = __ldg(&g_cc[j]) - 2.0f * p;
            if (d < bestE) { bestE = d; bestI = j; }   // ascending j => first-index ties
        }
    }
    if (lane == 0) g_idx[row] = bestI;
}

// ---------------- 5: fused scatter (segment sums + counts) + x_d output + loss ----------------
__global__ void scatter_out_kernel(const float* __restrict__ x, const float* __restrict__ cb,
                                   float* __restrict__ out) {
    int gi = (blockIdx.x * 256 + threadIdx.x) << 2;
    int n = gi >> 19;
    int rem = gi & (CT - 1);
    int c = rem >> 10;
    int t = rem & 1023;
    int row = (n << 10) + t;
    float4 xv = *(const float4*)(x + gi);
    int4 idx = *(const int4*)(g_idx + row);

    // segment sums (+ counts from the c==0 slice)
    atomicAdd(&g_nsum[idx.x * Cdim + c], xv.x);
    atomicAdd(&g_nsum[idx.y * Cdim + c], xv.y);
    atomicAdd(&g_nsum[idx.z * Cdim + c], xv.z);
    atomicAdd(&g_nsum[idx.w * Cdim + c], xv.w);
    if (c == 0) {
        atomicAdd(&g_ncnt[idx.x], 1.0f);
        atomicAdd(&g_ncnt[idx.y], 1.0f);
        atomicAdd(&g_ncnt[idx.z], 1.0f);
        atomicAdd(&g_ncnt[idx.w], 1.0f);
    }

    // x_d gather + write + commit loss partial
    float4 o;
    o.x = cb[(size_t)idx.x * Cdim + c];
    o.y = cb[(size_t)idx.y * Cdim + c];
    o.z = cb[(size_t)idx.z * Cdim + c];
    o.w = cb[(size_t)idx.w * Cdim + c];
    *(float4*)(out + OFF_XD + gi) = o;
    float dx = xv.x - o.x, dy = xv.y - o.y, dz = xv.z - o.z, dw = xv.w - o.w;
    float s = dx * dx + dy * dy + dz * dz + dw * dw;
    #pragma unroll
    for (int off = 16; off > 0; off >>= 1) s += __shfl_xor_sync(0xffffffffu, s, off);
    __shared__ float sh[8];
    int lane = threadIdx.x & 31, w = threadIdx.x >> 5;
    if (lane == 0) sh[w] = s;
    __syncthreads();
    if (threadIdx.x == 0) {
        float tot = 0.0f;
        #pragma unroll
        for (int i = 0; i < 8; i++) tot += sh[i];
        atomicAdd(&g_loss, tot);
    }
}

// ---------------- 6: EMA update + codebook reset + count out ----------------
__global__ void ema_kernel(const float* __restrict__ x,
                           const float* __restrict__ code_sum,
                           const float* __restrict__ code_count,
                           float* __restrict__ out) {
    int gi = blockIdx.x * 256 + threadIdx.x;
    int code = gi >> 9;
    int c = gi & 511;
    float cse = 0.99f * code_sum[gi] + 0.01f * g_nsum[gi];
    float cnt = 0.99f * code_count[code] + 0.01f * g_ncnt[code];
    out[OFF_CSE + gi] = cse;
    float ncb;
    if (cnt >= 1.0f) {
        ncb = cse / fmaxf(cnt, 1e-10f);
    } else {
        int t = code & 1023;
        int n = code >> 10;
        ncb = x[(size_t)n * CT + (size_t)c * Tdim + t];
    }
    out[OFF_CB + gi] = ncb;
    if (c == 0) out[OFF_CNT + code] = cnt;
}

// ---------------- 7: perplexity + loss finalize ----------------
__global__ void finalize_kernel(float* __restrict__ out) {
    float h = 0.0f;
    for (int code = threadIdx.x; code < NB; code += 256) {
        float p = g_ncnt[code] * (1.0f / 32768.0f);
        h += p * logf(p + 1e-7f);
    }
    #pragma unroll
    for (int off = 16; off > 0; off >>= 1) h += __shfl_xor_sync(0xffffffffu, h, off);
    __shared__ float sh[8];
    int lane = threadIdx.x & 31, w = threadIdx.x >> 5;
    if (lane == 0) sh[w] = h;
    __syncthreads();
    if (threadIdx.x == 0) {
        float tot = 0.0f;
        #pragma unroll
        for (int i = 0; i < 8; i++) tot += sh[i];
        out[OFF_PERP] = expf(-tot);
        out[OFF_LOSS] = g_loss * (1.0f / (float)XSZ);
    }
}

extern "C" void kernel_launch(void* const* d_in, const int* in_sizes, int n_in,
                              void* d_out, int out_size) {
    const float* x    = (const float*)d_in[0];
    const float* cb   = (const float*)d_in[1];
    const float* csum = (const float*)d_in[2];
    const float* ccnt = (const float*)d_in[3];
    float* out = (float*)d_out;

    cudaFuncSetAttribute(gemm_dhat, cudaFuncAttributeMaxDynamicSharedMemorySize, SMEM_BYTES);

    zero_kernel       <<<(NB * Cdim + 255) / 256, 256>>>();
    norms_kernel      <<<NB / 8, 256>>>(cb);
    transpose_kernel  <<<Ndim * 32 * 16, 256>>>(x);
    gemm_dhat         <<<NT / BM, 256, SMEM_BYTES>>>(x, cb);
    rescue_kernel     <<<NT / 8, 256>>>(cb);
    scatter_out_kernel<<<XSZ / 4 / 256, 256>>>(x, cb, out);
    ema_kernel        <<<NB * Cdim / 256, 256>>>(x, csum, ccnt, out);
    finalize_kernel   <<<1, 256>>>(out);
}

// round 9
// speedup vs baseline: 1.3303x; 1.0333x over previous
#include <cuda_runtime.h>
#include <cuda_fp16.h>
#include <math.h>
#include <cstdint>

#define Ndim 32
#define Cdim 512
#define Tdim 1024
#define NT   32768
#define NB   2048
#define CT   (Cdim*Tdim)
#define XSZ  (Ndim*Cdim*Tdim)

#define OFF_XD   0
#define OFF_LOSS 16777216
#define OFF_PERP 16777217
#define OFF_CB   16777218
#define OFF_CSE  (OFF_CB + NB*Cdim)
#define OFF_CNT  (OFF_CSE + NB*Cdim)

// Scratch (device globals: the sanctioned no-cudaMalloc path)
__device__ __align__(16) float g_cc[NB];
__device__ __align__(16) int   g_idx[NT];
__device__ __align__(16) float g_nsum[NB*Cdim];
__device__ __align__(16) float g_ncnt[NB];
__device__ float g_loss;
__device__ __align__(16) __half g_dhat[(size_t)NT * NB];  // 128 MB fp16 approx distances
__device__ __align__(16) float g_xT[(size_t)NT * Cdim];   // 64 MB x transposed [row][c]

// ---------------------------------------------------------------- helpers
__device__ __forceinline__ void cp_async16(uint32_t saddr, const void* g) {
    asm volatile("cp.async.ca.shared.global [%0], [%1], 16;" :: "r"(saddr), "l"(g));
}
__device__ __forceinline__ void cp_commit() {
    asm volatile("cp.async.commit_group;" ::: "memory");
}
__device__ __forceinline__ void mma_tf32(float* d, const uint32_t* a, const uint32_t* b) {
    asm volatile(
        "mma.sync.aligned.m16n8k8.row.col.f32.tf32.tf32.f32 "
        "{%0,%1,%2,%3}, {%4,%5,%6,%7}, {%8,%9}, {%0,%1,%2,%3};"
        : "+f"(d[0]), "+f"(d[1]), "+f"(d[2]), "+f"(d[3])
        : "r"(a[0]), "r"(a[1]), "r"(a[2]), "r"(a[3]), "r"(b[0]), "r"(b[1]));
}

// ---------------- 0: zero scratch ----------------
__global__ void zero_kernel() {
    int i = blockIdx.x * 256 + threadIdx.x;
    if (i < NB * Cdim) g_nsum[i] = 0.0f;
    if (i < NB)        g_ncnt[i] = 0.0f;
    if (i == 0)        g_loss = 0.0f;
}

// ---------------- 1: codebook squared norms ----------------
__global__ void norms_kernel(const float* __restrict__ cb) {
    int warp = threadIdx.x >> 5, lane = threadIdx.x & 31;
    int code = blockIdx.x * 8 + warp;
    const float* row = cb + (size_t)code * Cdim;
    float s = 0.0f;
    for (int j = lane; j < Cdim; j += 32) { float v = row[j]; s += v * v; }
    #pragma unroll
    for (int o = 16; o > 0; o >>= 1) s += __shfl_xor_sync(0xffffffffu, s, o);
    if (lane == 0) g_cc[code] = s;
}

// ---------------- 2: transpose x -> xT[row][c] ----------------
__global__ void transpose_kernel(const float* __restrict__ x) {
    __shared__ float s[32][33];
    int b = blockIdx.x;
    int ct = b & 15;          // c tile (16)
    int tt = (b >> 4) & 31;   // t tile (32)
    int n  = b >> 9;          // batch (32)
    int tid = threadIdx.x;
    int l5 = tid & 31, h3 = tid >> 5;
    #pragma unroll
    for (int q = 0; q < 4; q++) {
        int c_l = h3 + q * 8;
        s[c_l][l5] = x[(size_t)n * CT + (size_t)(ct * 32 + c_l) * Tdim + tt * 32 + l5];
    }
    __syncthreads();
    #pragma unroll
    for (int q = 0; q < 4; q++) {
        int t_l = h3 + q * 8;
        g_xT[(size_t)(n * 1024 + tt * 32 + t_l) * Cdim + ct * 32 + l5] = s[l5][t_l];
    }
}

// ---------------- 3: TF32 mma.sync screen GEMM -> d_hat (fp16) ----------------
// BM=128 rows x all 2048 codes (16 n-tiles of 128), BK=32, double-buffered cp.async.
// Mainloop VERBATIM from the 589.5us / 38.6%-tensor proven binary — do not edit.
// Epilogue: same structure, stores packed __half2 instead of float2.
#define BM 128
#define BN 128
#define BK 32
#define AS_STRIDE 136
#define BS_STRIDE 36
#define AS_FLOATS (BK * AS_STRIDE)                 // 4352
#define BS_FLOATS (BN * BS_STRIDE)                 // 4608
#define SMEM_BYTES ((2*AS_FLOATS + 2*BS_FLOATS)*4) // 71680

__global__ __launch_bounds__(256, 2) void gemm_dhat(const float* __restrict__ x,
                                                    const float* __restrict__ cb) {
    extern __shared__ float sm[];
    float* As[2] = { sm, sm + AS_FLOATS };
    float* Bs[2] = { sm + 2*AS_FLOATS, sm + 2*AS_FLOATS + BS_FLOATS };
    uint32_t smbase = (uint32_t)__cvta_generic_to_shared(sm);
    uint32_t smA[2] = { smbase, smbase + AS_FLOATS*4u };
    uint32_t smB[2] = { smbase + 2u*AS_FLOATS*4u, smbase + (2u*AS_FLOATS + BS_FLOATS)*4u };

    int tid = threadIdx.x, lane = tid & 31, wid = tid >> 5;
    int wm = wid >> 2, wn = wid & 3;       // warp grid 2 (m) x 4 (n)
    int lq = lane & 3, lr = lane >> 2;
    int r0 = blockIdx.x * BM;
    const float* xb = x + (size_t)(r0 >> 10) * CT + (r0 & 1023);

    int a_p  = (tid & 31) << 2;  // float offset within a k-row (0..124)
    int a_kb = tid >> 5;         // base k (0..7)
    int b_kp = (tid & 7) << 2;   // float offset within code row
    int b_cb = tid >> 3;         // base code (0..31)

    float acc[4][4][4];
    #pragma unroll
    for (int mi = 0; mi < 4; mi++)
        #pragma unroll
        for (int ni = 0; ni < 4; ni++)
            #pragma unroll
            for (int v = 0; v < 4; v++) acc[mi][ni][v] = 0.0f;

    auto load_tiles = [&](int buf, int nt, int kc) {
        #pragma unroll
        for (int it = 0; it < 4; it++) {
            int k = a_kb + it * 8;
            cp_async16(smA[buf] + (uint32_t)(k * AS_STRIDE + a_p) * 4u,
                       xb + (size_t)(kc + k) * Tdim + a_p);
        }
        #pragma unroll
        for (int it = 0; it < 4; it++) {
            int code = b_cb + it * 32;
            cp_async16(smB[buf] + (uint32_t)(code * BS_STRIDE + b_kp) * 4u,
                       cb + (size_t)(nt + code) * Cdim + kc + b_kp);
        }
        cp_commit();
    };

    load_tiles(0, 0, 0);

    for (int i = 0; i < 256; i++) {            // (nt, kc) flattened: 16 x 16
        int nxt = i + 1;
        if (nxt < 256) {
            load_tiles(nxt & 1, (nxt >> 4) * 128, (nxt & 15) * 32);
            asm volatile("cp.async.wait_group 1;" ::: "memory");
        } else {
            asm volatile("cp.async.wait_group 0;" ::: "memory");
        }
        __syncthreads();

        const float* A = As[i & 1];
        const float* B = Bs[i & 1];
        #pragma unroll
        for (int kk = 0; kk < 4; kk++) {
            uint32_t a[4][4], b[4][2];
            #pragma unroll
            for (int mi = 0; mi < 4; mi++) {
                const float* ap = A + (kk * 8 + lq) * AS_STRIDE + wm * 64 + mi * 16 + lr;
                a[mi][0] = __float_as_uint(ap[0]);
                a[mi][1] = __float_as_uint(ap[8]);
                a[mi][2] = __float_as_uint(ap[4 * AS_STRIDE]);
                a[mi][3] = __float_as_uint(ap[4 * AS_STRIDE + 8]);
            }
            #pragma unroll
            for (int ni = 0; ni < 4; ni++) {
                const float* bp = B + (wn * 32 + ni * 8 + lr) * BS_STRIDE + kk * 8 + lq;
                b[ni][0] = __float_as_uint(bp[0]);
                b[ni][1] = __float_as_uint(bp[4]);
            }
            #pragma unroll
            for (int mi = 0; mi < 4; mi++)
                #pragma unroll
                for (int ni = 0; ni < 4; ni++)
                    mma_tf32(acc[mi][ni], a[mi], b[ni]);
        }

        if ((i & 15) == 15) {  // end of K for this n-tile: spill d_hat (fp16), reset accs
            int nt = (i >> 4) * 128;
            #pragma unroll
            for (int mi = 0; mi < 4; mi++) {
                int row = r0 + wm * 64 + mi * 16 + lr;
                #pragma unroll
                for (int ni = 0; ni < 4; ni++) {
                    int col = nt + wn * 32 + ni * 8 + 2 * lq;
                    float cc0 = __ldg(&g_cc[col]);
                    float cc1 = __ldg(&g_cc[col + 1]);
                    float2 v0 = make_float2(cc0 - 2.0f * acc[mi][ni][0],
                                            cc1 - 2.0f * acc[mi][ni][1]);
                    float2 v1 = make_float2(cc0 - 2.0f * acc[mi][ni][2],
                                            cc1 - 2.0f * acc[mi][ni][3]);
                    *(__half2*)&g_dhat[(size_t)row * NB + col] = __float22half2_rn(v0);
                    *(__half2*)&g_dhat[(size_t)(row + 8) * NB + col] = __float22half2_rn(v1);
                    acc[mi][ni][0] = acc[mi][ni][1] = acc[mi][ni][2] = acc[mi][ni][3] = 0.0f;
                }
            }
        }
        __syncthreads();
    }
}

// ---------------- 4: rescue — exact fp32 argmin among margin candidates (fp16 d_hat) ----------------
// Screen error: tf32 <= 2.7 each side + fp16 quant 0.25 each side => 5.9 < margin 8.0.
__global__ void rescue_kernel(const float* __restrict__ cb) {
    int wid = threadIdx.x >> 5, lane = threadIdx.x & 31;
    int row = blockIdx.x * 8 + wid;

    float xr[16];
    #pragma unroll
    for (int q = 0; q < 16; q++)
        xr[q] = g_xT[(size_t)row * Cdim + lane + q * 32];

    const __half2* drow = (const __half2*)&g_dhat[(size_t)row * NB];
    float2 dv[32];
    #pragma unroll
    for (int i = 0; i < 32; i++)
        dv[i] = __half22float2(drow[lane + i * 32]);   // codes 2*(lane+i*32), +1

    float bv = fminf(dv[0].x, dv[0].y);
    #pragma unroll
    for (int i = 1; i < 32; i++) bv = fminf(bv, fminf(dv[i].x, dv[i].y));
    #pragma unroll
    for (int o = 16; o > 0; o >>= 1) bv = fminf(bv, __shfl_xor_sync(0xffffffffu, bv, o));

    float thr = bv + 8.0f;
    float bestE = 3.0e38f;
    int   bestI = 0x7fffffff;

    auto exact = [&](int j) {
        const float* crow = cb + (size_t)j * Cdim;
        float p = 0.0f;
        #pragma unroll
        for (int q = 0; q < 16; q++)
            p += xr[q] * __ldg(&crow[lane + q * 32]);
        #pragma unroll
        for (int o = 16; o > 0; o >>= 1) p += __shfl_xor_sync(0xffffffffu, p, o);
        float d = __ldg(&g_cc[j]) - 2.0f * p;
        if (d < bestE || (d == bestE && j < bestI)) { bestE = d; bestI = j; }
    };

    #pragma unroll 4
    for (int i = 0; i < 32; i++) {
        unsigned mlo = __ballot_sync(0xffffffffu, dv[i].x <= thr);
        unsigned mhi = __ballot_sync(0xffffffffu, dv[i].y <= thr);
        while (mlo) { int s = __ffs(mlo) - 1; mlo &= mlo - 1; exact((i * 32 + s) * 2); }
        while (mhi) { int s = __ffs(mhi) - 1; mhi &= mhi - 1; exact((i * 32 + s) * 2 + 1); }
    }
    if (lane == 0) g_idx[row] = bestI;
}

// ---------------- 5: fused scatter (segment sums + counts) + x_d output + loss ----------------
__global__ void scatter_out_kernel(const float* __restrict__ x, const float* __restrict__ cb,
                                   float* __restrict__ out) {
    int gi = (blockIdx.x * 256 + threadIdx.x) << 2;
    int n = gi >> 19;
    int rem = gi & (CT - 1);
    int c = rem >> 10;
    int t = rem & 1023;
    int row = (n << 10) + t;
    float4 xv = *(const float4*)(x + gi);
    int4 idx = *(const int4*)(g_idx + row);

    // segment sums (+ counts from the c==0 slice)
    atomicAdd(&g_nsum[idx.x * Cdim + c], xv.x);
    atomicAdd(&g_nsum[idx.y * Cdim + c], xv.y);
    atomicAdd(&g_nsum[idx.z * Cdim + c], xv.z);
    atomicAdd(&g_nsum[idx.w * Cdim + c], xv.w);
    if (c == 0) {
        atomicAdd(&g_ncnt[idx.x], 1.0f);
        atomicAdd(&g_ncnt[idx.y], 1.0f);
        atomicAdd(&g_ncnt[idx.z], 1.0f);
        atomicAdd(&g_ncnt[idx.w], 1.0f);
    }

    // x_d gather + write + commit loss partial
    float4 o;
    o.x = cb[(size_t)idx.x * Cdim + c];
    o.y = cb[(size_t)idx.y * Cdim + c];
    o.z = cb[(size_t)idx.z * Cdim + c];
    o.w = cb[(size_t)idx.w * Cdim + c];
    *(float4*)(out + OFF_XD + gi) = o;
    float dx = xv.x - o.x, dy = xv.y - o.y, dz = xv.z - o.z, dw = xv.w - o.w;
    float s = dx * dx + dy * dy + dz * dz + dw * dw;
    #pragma unroll
    for (int off = 16; off > 0; off >>= 1) s += __shfl_xor_sync(0xffffffffu, s, off);
    __shared__ float sh[8];
    int lane = threadIdx.x & 31, w = threadIdx.x >> 5;
    if (lane == 0) sh[w] = s;
    __syncthreads();
    if (threadIdx.x == 0) {
        float tot = 0.0f;
        #pragma unroll
        for (int i = 0; i < 8; i++) tot += sh[i];
        atomicAdd(&g_loss, tot);
    }
}

// ---------------- 6: EMA update + codebook reset + count out ----------------
__global__ void ema_kernel(const float* __restrict__ x,
                           const float* __restrict__ code_sum,
                           const float* __restrict__ code_count,
                           float* __restrict__ out) {
    int gi = blockIdx.x * 256 + threadIdx.x;
    int code = gi >> 9;
    int c = gi & 511;
    float cse = 0.99f * code_sum[gi] + 0.01f * g_nsum[gi];
    float cnt = 0.99f * code_count[code] + 0.01f * g_ncnt[code];
    out[OFF_CSE + gi] = cse;
    float ncb;
    if (cnt >= 1.0f) {
        ncb = cse / fmaxf(cnt, 1e-10f);
    } else {
        int t = code & 1023;
        int n = code >> 10;
        ncb = x[(size_t)n * CT + (size_t)c * Tdim + t];
    }
    out[OFF_CB + gi] = ncb;
    if (c == 0) out[OFF_CNT + code] = cnt;
}

// ---------------- 7: perplexity + loss finalize ----------------
__global__ void finalize_kernel(float* __restrict__ out) {
    float h = 0.0f;
    for (int code = threadIdx.x; code < NB; code += 256) {
        float p = g_ncnt[code] * (1.0f / 32768.0f);
        h += p * logf(p + 1e-7f);
    }
    #pragma unroll
    for (int off = 16; off > 0; off >>= 1) h += __shfl_xor_sync(0xffffffffu, h, off);
    __shared__ float sh[8];
    int lane = threadIdx.x & 31, w = threadIdx.x >> 5;
    if (lane == 0) sh[w] = h;
    __syncthreads();
    if (threadIdx.x == 0) {
        float tot = 0.0f;
        #pragma unroll
        for (int i = 0; i < 8; i++) tot += sh[i];
        out[OFF_PERP] = expf(-tot);
        out[OFF_LOSS] = g_loss * (1.0f / (float)XSZ);
    }
}

extern "C" void kernel_launch(void* const* d_in, const int* in_sizes, int n_in,
                              void* d_out, int out_size) {
    const float* x    = (const float*)d_in[0];
    const float* cb   = (const float*)d_in[1];
    const float* csum = (const float*)d_in[2];
    const float* ccnt = (const float*)d_in[3];
    float* out = (float*)d_out;

    cudaFuncSetAttribute(gemm_dhat, cudaFuncAttributeMaxDynamicSharedMemorySize, SMEM_BYTES);

    zero_kernel       <<<(NB * Cdim + 255) / 256, 256>>>();
    norms_kernel      <<<NB / 8, 256>>>(cb);
    transpose_kernel  <<<Ndim * 32 * 16, 256>>>(x);
    gemm_dhat         <<<NT / BM, 256, SMEM_BYTES>>>(x, cb);
    rescue_kernel     <<<NT / 8, 256>>>(cb);
    scatter_out_kernel<<<XSZ / 4 / 256, 256>>>(x, cb, out);
    ema_kernel        <<<NB * Cdim / 256, 256>>>(x, csum, ccnt, out);
    finalize_kernel   <<<1, 256>>>(out);
}

// round 11
// speedup vs baseline: 1.4185x; 1.0663x over previous
#include <cuda_runtime.h>
#include <cuda_fp16.h>
#include <math.h>
#include <cstdint>

#define Ndim 32
#define Cdim 512
#define Tdim 1024
#define NT   32768
#define NB   2048
#define CT   (Cdim*Tdim)
#define XSZ  (Ndim*Cdim*Tdim)

#define OFF_XD   0
#define OFF_LOSS 16777216
#define OFF_PERP 16777217
#define OFF_CB   16777218
#define OFF_CSE  (OFF_CB + NB*Cdim)
#define OFF_CNT  (OFF_CSE + NB*Cdim)

// Scratch (device globals: the sanctioned no-cudaMalloc path)
__device__ __align__(16) float g_cc[NB];
__device__ __align__(16) int   g_idx[NT];
__device__ __align__(16) float g_nsum[NB*Cdim];
__device__ __align__(16) float g_ncnt[NB];
__device__ float g_loss;
__device__ __align__(16) __half g_dhat[(size_t)NT * NB];  // 128 MB fp16 approx distances
__device__ __align__(16) float g_xT[(size_t)NT * Cdim];   // 64 MB x transposed [row][c]

// ---------------------------------------------------------------- helpers
__device__ __forceinline__ void cp_async16(uint32_t saddr, const void* g) {
    asm volatile("cp.async.ca.shared.global [%0], [%1], 16;" :: "r"(saddr), "l"(g));
}
__device__ __forceinline__ void cp_commit() {
    asm volatile("cp.async.commit_group;" ::: "memory");
}
__device__ __forceinline__ void mma_tf32(float* d, const uint32_t* a, const uint32_t* b) {
    asm volatile(
        "mma.sync.aligned.m16n8k8.row.col.f32.tf32.tf32.f32 "
        "{%0,%1,%2,%3}, {%4,%5,%6,%7}, {%8,%9}, {%0,%1,%2,%3};"
        : "+f"(d[0]), "+f"(d[1]), "+f"(d[2]), "+f"(d[3])
        : "r"(a[0]), "r"(a[1]), "r"(a[2]), "r"(a[3]), "r"(b[0]), "r"(b[1]));
}

// ---------------- 0: zero scratch ----------------
__global__ void zero_kernel() {
    int i = blockIdx.x * 256 + threadIdx.x;
    if (i < NB * Cdim) g_nsum[i] = 0.0f;
    if (i < NB)        g_ncnt[i] = 0.0f;
    if (i == 0)        g_loss = 0.0f;
}

// ---------------- 1: codebook squared norms ----------------
__global__ void norms_kernel(const float* __restrict__ cb) {
    int warp = threadIdx.x >> 5, lane = threadIdx.x & 31;
    int code = blockIdx.x * 8 + warp;
    const float* row = cb + (size_t)code * Cdim;
    float s = 0.0f;
    for (int j = lane; j < Cdim; j += 32) { float v = row[j]; s += v * v; }
    #pragma unroll
    for (int o = 16; o > 0; o >>= 1) s += __shfl_xor_sync(0xffffffffu, s, o);
    if (lane == 0) g_cc[code] = s;
}

// ---------------- 2: transpose x -> xT[row][c] ----------------
__global__ void transpose_kernel(const float* __restrict__ x) {
    __shared__ float s[32][33];
    int b = blockIdx.x;
    int ct = b & 15;          // c tile (16)
    int tt = (b >> 4) & 31;   // t tile (32)
    int n  = b >> 9;          // batch (32)
    int tid = threadIdx.x;
    int l5 = tid & 31, h3 = tid >> 5;
    #pragma unroll
    for (int q = 0; q < 4; q++) {
        int c_l = h3 + q * 8;
        s[c_l][l5] = x[(size_t)n * CT + (size_t)(ct * 32 + c_l) * Tdim + tt * 32 + l5];
    }
    __syncthreads();
    #pragma unroll
    for (int q = 0; q < 4; q++) {
        int t_l = h3 + q * 8;
        g_xT[(size_t)(n * 1024 + tt * 32 + t_l) * Cdim + ct * 32 + l5] = s[l5][t_l];
    }
}

// ---------------- 3: TF32 mma.sync screen GEMM -> d_hat (fp16) ----------------
// 3-stage cp.async pipeline, ONE barrier per iter (top), loads-after-barrier,
// wait_group 1 (+ prologue wait) => every stage-i read is preceded across all
// threads by a pre-barrier wait covering its data. Compute body + fp16 spill
// epilogue identical to the proven R9 kernel.
#define BM 128
#define BN 128
#define BK 32
#define AS_STRIDE 136
#define BS_STRIDE 36
#define AS_FLOATS (BK * AS_STRIDE)                 // 4352
#define BS_FLOATS (BN * BS_STRIDE)                 // 4608
#define STAGE_FLOATS (AS_FLOATS + BS_FLOATS)       // 8960
#define SMEM_BYTES (3 * STAGE_FLOATS * 4)          // 107520

__global__ __launch_bounds__(256, 2) void gemm_dhat(const float* __restrict__ x,
                                                    const float* __restrict__ cb) {
    extern __shared__ float sm[];
    uint32_t smbase = (uint32_t)__cvta_generic_to_shared(sm);

    int tid = threadIdx.x, lane = tid & 31, wid = tid >> 5;
    int wm = wid >> 2, wn = wid & 3;       // warp grid 2 (m) x 4 (n)
    int lq = lane & 3, lr = lane >> 2;
    int r0 = blockIdx.x * BM;
    const float* xb = x + (size_t)(r0 >> 10) * CT + (r0 & 1023);

    int a_p  = (tid & 31) << 2;  // float offset within a k-row (0..124)
    int a_kb = tid >> 5;         // base k (0..7)
    int b_kp = (tid & 7) << 2;   // float offset within code row
    int b_cb = tid >> 3;         // base code (0..31)

    float acc[4][4][4];
    #pragma unroll
    for (int mi = 0; mi < 4; mi++)
        #pragma unroll
        for (int ni = 0; ni < 4; ni++)
            #pragma unroll
            for (int v = 0; v < 4; v++) acc[mi][ni][v] = 0.0f;

    auto load_tiles = [&](int stage, int idx) {
        int nt = (idx >> 4) * 128, kc = (idx & 15) * 32;
        uint32_t sA = smbase + (uint32_t)(stage * STAGE_FLOATS) * 4u;
        uint32_t sB = sA + (uint32_t)AS_FLOATS * 4u;
        #pragma unroll
        for (int it = 0; it < 4; it++) {
            int k = a_kb + it * 8;
            cp_async16(sA + (uint32_t)(k * AS_STRIDE + a_p) * 4u,
                       xb + (size_t)(kc + k) * Tdim + a_p);
        }
        #pragma unroll
        for (int it = 0; it < 4; it++) {
            int code = b_cb + it * 32;
            cp_async16(sB + (uint32_t)(code * BS_STRIDE + b_kp) * 4u,
                       cb + (size_t)(nt + code) * Cdim + kc + b_kp);
        }
    };

    load_tiles(0, 0); cp_commit();
    load_tiles(1, 1); cp_commit();
    asm volatile("cp.async.wait_group 1;" ::: "memory");   // stage 0 landed (all threads, pre-bar)

    for (int i = 0; i < 256; i++) {            // (nt, kc) flattened: 16 x 16
        __syncthreads();                       // opens epoch i: stage i%3 published, overwrite-safe
        if (i + 2 < 256) load_tiles((i + 2) % 3, i + 2);
        cp_commit();
        asm volatile("cp.async.wait_group 1;" ::: "memory");  // data <= i+1 landed (this thread)

        const float* A = sm + (i % 3) * STAGE_FLOATS;
        const float* B = A + AS_FLOATS;
        #pragma unroll
        for (int kk = 0; kk < 4; kk++) {
            uint32_t a[4][4], b[4][2];
            #pragma unroll
            for (int mi = 0; mi < 4; mi++) {
                const float* ap = A + (kk * 8 + lq) * AS_STRIDE + wm * 64 + mi * 16 + lr;
                a[mi][0] = __float_as_uint(ap[0]);
                a[mi][1] = __float_as_uint(ap[8]);
                a[mi][2] = __float_as_uint(ap[4 * AS_STRIDE]);
                a[mi][3] = __float_as_uint(ap[4 * AS_STRIDE + 8]);
            }
            #pragma unroll
            for (int ni = 0; ni < 4; ni++) {
                const float* bp = B + (wn * 32 + ni * 8 + lr) * BS_STRIDE + kk * 8 + lq;
                b[ni][0] = __float_as_uint(bp[0]);
                b[ni][1] = __float_as_uint(bp[4]);
            }
            #pragma unroll
            for (int mi = 0; mi < 4; mi++)
                #pragma unroll
                for (int ni = 0; ni < 4; ni++)
                    mma_tf32(acc[mi][ni], a[mi], b[ni]);
        }

        if ((i & 15) == 15) {  // end of K for this n-tile: spill d_hat (fp16), reset accs
            int nt = (i >> 4) * 128;
            #pragma unroll
            for (int mi = 0; mi < 4; mi++) {
                int row = r0 + wm * 64 + mi * 16 + lr;
                #pragma unroll
                for (int ni = 0; ni < 4; ni++) {
                    int col = nt + wn * 32 + ni * 8 + 2 * lq;
                    float cc0 = __ldg(&g_cc[col]);
                    float cc1 = __ldg(&g_cc[col + 1]);
                    float2 v0 = make_float2(cc0 - 2.0f * acc[mi][ni][0],
                                            cc1 - 2.0f * acc[mi][ni][1]);
                    float2 v1 = make_float2(cc0 - 2.0f * acc[mi][ni][2],
                                            cc1 - 2.0f * acc[mi][ni][3]);
                    *(__half2*)&g_dhat[(size_t)row * NB + col] = __float22half2_rn(v0);
                    *(__half2*)&g_dhat[(size_t)(row + 8) * NB + col] = __float22half2_rn(v1);
                    acc[mi][ni][0] = acc[mi][ni][1] = acc[mi][ni][2] = acc[mi][ni][3] = 0.0f;
                }
            }
        }
    }
}

// ---------------- 4: rescue — exact fp32 argmin among margin candidates (fp16 d_hat) ----------------
// Screen error: tf32 <= 2.7 each side + fp16 quant 0.25 each side => 5.9 < margin 8.0.
__global__ void rescue_kernel(const float* __restrict__ cb) {
    int wid = threadIdx.x >> 5, lane = threadIdx.x & 31;
    int row = blockIdx.x * 8 + wid;

    float xr[16];
    #pragma unroll
    for (int q = 0; q < 16; q++)
        xr[q] = g_xT[(size_t)row * Cdim + lane + q * 32];

    const __half2* drow = (const __half2*)&g_dhat[(size_t)row * NB];
    float2 dv[32];
    #pragma unroll
    for (int i = 0; i < 32; i++)
        dv[i] = __half22float2(drow[lane + i * 32]);   // codes 2*(lane+i*32), +1

    float bv = fminf(dv[0].x, dv[0].y);
    #pragma unroll
    for (int i = 1; i < 32; i++) bv = fminf(bv, fminf(dv[i].x, dv[i].y));
    #pragma unroll
    for (int o = 16; o > 0; o >>= 1) bv = fminf(bv, __shfl_xor_sync(0xffffffffu, bv, o));

    float thr = bv + 8.0f;
    float bestE = 3.0e38f;
    int   bestI = 0x7fffffff;

    auto exact = [&](int j) {
        const float* crow = cb + (size_t)j * Cdim;
        float p = 0.0f;
        #pragma unroll
        for (int q = 0; q < 16; q++)
            p += xr[q] * __ldg(&crow[lane + q * 32]);
        #pragma unroll
        for (int o = 16; o > 0; o >>= 1) p += __shfl_xor_sync(0xffffffffu, p, o);
        float d = __ldg(&g_cc[j]) - 2.0f * p;
        if (d < bestE || (d == bestE && j < bestI)) { bestE = d; bestI = j; }
    };

    #pragma unroll 4
    for (int i = 0; i < 32; i++) {
        unsigned mlo = __ballot_sync(0xffffffffu, dv[i].x <= thr);
        unsigned mhi = __ballot_sync(0xffffffffu, dv[i].y <= thr);
        while (mlo) { int s = __ffs(mlo) - 1; mlo &= mlo - 1; exact((i * 32 + s) * 2); }
        while (mhi) { int s = __ffs(mhi) - 1; mhi &= mhi - 1; exact((i * 32 + s) * 2 + 1); }
    }
    if (lane == 0) g_idx[row] = bestI;
}

// ---------------- 5: fused scatter (segment sums + counts) + x_d output + loss ----------------
__global__ void scatter_out_kernel(const float* __restrict__ x, const float* __restrict__ cb,
                                   float* __restrict__ out) {
    int gi = (blockIdx.x * 256 + threadIdx.x) << 2;
    int n = gi >> 19;
    int rem = gi & (CT - 1);
    int c = rem >> 10;
    int t = rem & 1023;
    int row = (n << 10) + t;
    float4 xv = *(const float4*)(x + gi);
    int4 idx = *(const int4*)(g_idx + row);

    // segment sums (+ counts from the c==0 slice)
    atomicAdd(&g_nsum[idx.x * Cdim + c], xv.x);
    atomicAdd(&g_nsum[idx.y * Cdim + c], xv.y);
    atomicAdd(&g_nsum[idx.z * Cdim + c], xv.z);
    atomicAdd(&g_nsum[idx.w * Cdim + c], xv.w);
    if (c == 0) {
        atomicAdd(&g_ncnt[idx.x], 1.0f);
        atomicAdd(&g_ncnt[idx.y], 1.0f);
        atomicAdd(&g_ncnt[idx.z], 1.0f);
        atomicAdd(&g_ncnt[idx.w], 1.0f);
    }

    // x_d gather + write + commit loss partial
    float4 o;
    o.x = cb[(size_t)idx.x * Cdim + c];
    o.y = cb[(size_t)idx.y * Cdim + c];
    o.z = cb[(size_t)idx.z * Cdim + c];
    o.w = cb[(size_t)idx.w * Cdim + c];
    *(float4*)(out + OFF_XD + gi) = o;
    float dx = xv.x - o.x, dy = xv.y - o.y, dz = xv.z - o.z, dw = xv.w - o.w;
    float s = dx * dx + dy * dy + dz * dz + dw * dw;
    #pragma unroll
    for (int off = 16; off > 0; off >>= 1) s += __shfl_xor_sync(0xffffffffu, s, off);
    __shared__ float sh[8];
    int lane = threadIdx.x & 31, w = threadIdx.x >> 5;
    if (lane == 0) sh[w] = s;
    __syncthreads();
    if (threadIdx.x == 0) {
        float tot = 0.0f;
        #pragma unroll
        for (int i = 0; i < 8; i++) tot += sh[i];
        atomicAdd(&g_loss, tot);
    }
}

// ---------------- 6: EMA update + codebook reset + count out ----------------
__global__ void ema_kernel(const float* __restrict__ x,
                           const float* __restrict__ code_sum,
                           const float* __restrict__ code_count,
                           float* __restrict__ out) {
    int gi = blockIdx.x * 256 + threadIdx.x;
    int code = gi >> 9;
    int c = gi & 511;
    float cse = 0.99f * code_sum[gi] + 0.01f * g_nsum[gi];
    float cnt = 0.99f * code_count[code] + 0.01f * g_ncnt[code];
    out[OFF_CSE + gi] = cse;
    float ncb;
    if (cnt >= 1.0f) {
        ncb = cse / fmaxf(cnt, 1e-10f);
    } else {
        int t = code & 1023;
        int n = code >> 10;
        ncb = x[(size_t)n * CT + (size_t)c * Tdim + t];
    }
    out[OFF_CB + gi] = ncb;
    if (c == 0) out[OFF_CNT + code] = cnt;
}

// ---------------- 7: perplexity + loss finalize ----------------
__global__ void finalize_kernel(float* __restrict__ out) {
    float h = 0.0f;
    for (int code = threadIdx.x; code < NB; code += 256) {
        float p = g_ncnt[code] * (1.0f / 32768.0f);
        h += p * logf(p + 1e-7f);
    }
    #pragma unroll
    for (int off = 16; off > 0; off >>= 1) h += __shfl_xor_sync(0xffffffffu, h, off);
    __shared__ float sh[8];
    int lane = threadIdx.x & 31, w = threadIdx.x >> 5;
    if (lane == 0) sh[w] = h;
    __syncthreads();
    if (threadIdx.x == 0) {
        float tot = 0.0f;
        #pragma unroll
        for (int i = 0; i < 8; i++) tot += sh[i];
        out[OFF_PERP] = expf(-tot);
        out[OFF_LOSS] = g_loss * (1.0f / (float)XSZ);
    }
}

extern "C" void kernel_launch(void* const* d_in, const int* in_sizes, int n_in,
                              void* d_out, int out_size) {
    const float* x    = (const float*)d_in[0];
    const float* cb   = (const float*)d_in[1];
    const float* csum = (const float*)d_in[2];
    const float* ccnt = (const float*)d_in[3];
    float* out = (float*)d_out;

    cudaFuncSetAttribute(gemm_dhat, cudaFuncAttributeMaxDynamicSharedMemorySize, SMEM_BYTES);

    zero_kernel       <<<(NB * Cdim + 255) / 256, 256>>>();
    norms_kernel      <<<NB / 8, 256>>>(cb);
    transpose_kernel  <<<Ndim * 32 * 16, 256>>>(x);
    gemm_dhat         <<<NT / BM, 256, SMEM_BYTES>>>(x, cb);
    rescue_kernel     <<<NT / 8, 256>>>(cb);
    scatter_out_kernel<<<XSZ / 4 / 256, 256>>>(x, cb, out);
    ema_kernel        <<<NB * Cdim / 256, 256>>>(x, csum, ccnt, out);
    finalize_kernel   <<<1, 256>>>(out);
}